// round 16
// baseline (speedup 1.0000x reference)
#include <cuda_runtime.h>
#include <cuda_bf16.h>
#include <cstdint>

constexpr int Hc = 128, Wc = 128, HWc = Hc * Wc;
constexpr int HP = 130;   // padded spatial dim

// ---------------- scratch (device globals; no allocation allowed) ----------------
__device__ float g_po[2 * 432 * HWc];
__device__ float g_xt[2 * 16 * HWc * 4];
__device__ float g_dp[4 * 2 * 64 * HWc];
__device__ __nv_bfloat16 g_efph[2 * HP * HP * 128];
__device__ __nv_bfloat16 g_efpl[2 * HP * HP * 128];
__device__ __nv_bfloat16 g_h1ph[2 * HP * HP * 64];
__device__ __nv_bfloat16 g_h1pl[2 * HP * HP * 64];
__device__ __nv_bfloat16 g_h2ph[2 * HP * HP * 64];
__device__ __nv_bfloat16 g_h2pl[2 * HP * HP * 64];
__device__ __nv_bfloat16 g_w1bh[9 * 64 * 128];
__device__ __nv_bfloat16 g_w1bl[9 * 64 * 128];
__device__ __nv_bfloat16 g_w2bh[9 * 64 * 64];
__device__ __nv_bfloat16 g_w2bl[9 * 64 * 64];
__device__ __nv_bfloat16 g_w3bh[9 * 432 * 64];
__device__ __nv_bfloat16 g_w3bl[9 * 432 * 64];
__device__ __nv_bfloat16 g_wdh[16 * 64 * 48];
__device__ __nv_bfloat16 g_wdl[16 * 64 * 48];

// ---------------- warp MMA helpers ----------------
__device__ __forceinline__ uint32_t smem_to_u32(const void* p) {
    uint32_t a;
    asm("{ .reg .u64 t; cvta.to.shared.u64 t, %1; cvt.u32.u64 %0, t; }" : "=r"(a) : "l"(p));
    return a;
}
__device__ __forceinline__ void ldsm_x4(uint32_t (&r)[4], uint32_t addr) {
    asm volatile("ldmatrix.sync.aligned.m8n8.x4.shared.b16 {%0,%1,%2,%3}, [%4];"
        : "=r"(r[0]), "=r"(r[1]), "=r"(r[2]), "=r"(r[3]) : "r"(addr));
}
__device__ __forceinline__ void ldsm_x2(uint32_t (&r)[2], uint32_t addr) {
    asm volatile("ldmatrix.sync.aligned.m8n8.x2.shared.b16 {%0,%1}, [%2];"
        : "=r"(r[0]), "=r"(r[1]) : "r"(addr));
}
__device__ __forceinline__ void mma_bf16(float (&c)[4], const uint32_t (&a)[4], const uint32_t (&bb)[2]) {
    asm volatile("mma.sync.aligned.m16n8k16.row.col.f32.bf16.bf16.f32 "
        "{%0,%1,%2,%3}, {%4,%5,%6,%7}, {%8,%9}, {%0,%1,%2,%3};"
        : "+f"(c[0]), "+f"(c[1]), "+f"(c[2]), "+f"(c[3])
        : "r"(a[0]), "r"(a[1]), "r"(a[2]), "r"(a[3]), "r"(bb[0]), "r"(bb[1]));
}
__device__ __forceinline__ void mma_bf16_2(float (&c)[4], const uint32_t (&a)[4], uint32_t b0, uint32_t b1) {
    asm volatile("mma.sync.aligned.m16n8k16.row.col.f32.bf16.bf16.f32 "
        "{%0,%1,%2,%3}, {%4,%5,%6,%7}, {%8,%9}, {%0,%1,%2,%3};"
        : "+f"(c[0]), "+f"(c[1]), "+f"(c[2]), "+f"(c[3])
        : "r"(a[0]), "r"(a[1]), "r"(a[2]), "r"(a[3]), "r"(b0), "r"(b1));
}

__device__ __forceinline__ void hilo_store(float v, __nv_bfloat16* wh, __nv_bfloat16* wl, int idx) {
    __nv_bfloat16 h = __float2bfloat16(v);
    wh[idx] = h;
    wl[idx] = __float2bfloat16(v - __bfloat162float(h));
}

__device__ __forceinline__ void border_yx(int p, int& y, int& x) {
    if (p < 130)      { y = 0;        x = p; }
    else if (p < 260) { y = 129;      x = p - 130; }
    else if (p < 388) { y = p - 259;  x = 0; }
    else              { y = p - 387;  x = 129; }
}

// ---------------- fused prep ----------------
constexpr int WSEG1 = 9 * 64 * 128;
constexpr int WSEG2 = 9 * 64 * 64;
constexpr int WSEG3 = 9 * 432 * 64;
constexpr int WSEG4 = 16 * 64 * 48;
constexpr int WTOT  = WSEG1 + WSEG2 + WSEG3 + WSEG4;

__global__ __launch_bounds__(256)
void prep_all_kernel(const float* __restrict__ x, float* __restrict__ xt,
                     const float* __restrict__ ef,
                     __nv_bfloat16* __restrict__ efh, __nv_bfloat16* __restrict__ efl,
                     __nv_bfloat16* h1h, __nv_bfloat16* h1l,
                     __nv_bfloat16* h2h, __nv_bfloat16* h2l,
                     const float* __restrict__ w1, const float* __restrict__ w2,
                     const float* __restrict__ w3, const float* __restrict__ wd,
                     __nv_bfloat16* wh1, __nv_bfloat16* wl1,
                     __nv_bfloat16* wh2, __nv_bfloat16* wl2,
                     __nv_bfloat16* wh3, __nv_bfloat16* wl3,
                     __nv_bfloat16* whd, __nv_bfloat16* wld,
                     int B, int t_end, int e_end, int f_end)
{
    const int blk = blockIdx.x;
    const int tid = threadIdx.x;
    if (blk < t_end) {
        int hw = (blk & 63) * 256 + tid;
        int g  = (blk >> 6) & 15;
        int b  = blk >> 10;
        const float* xp = x + ((size_t)b * 64 + g * 4) * HWc + hw;
        float4 v;
        v.x = xp[0];
        v.y = xp[HWc];
        v.z = xp[2 * HWc];
        v.w = xp[3 * HWc];
        reinterpret_cast<float4*>(xt + (((size_t)b * 16 + g) * HWc + hw) * 4)[0] = v;
    } else if (blk < e_end) {
        int j = blk - t_end;
        int hw = (j & 63) * 256 + tid;
        int g  = (j >> 6) & 31;
        int b  = j >> 11;
        int y = hw >> 7, xx = hw & 127;
        const float* p = ef + ((size_t)b * 128 + g * 4) * HWc + hw;
        size_t base = ((size_t)(b * HP + y + 1) * HP + (xx + 1)) * 128 + g * 4;
        #pragma unroll
        for (int c = 0; c < 4; c++) {
            float v = p[c * HWc];
            __nv_bfloat16 h = __float2bfloat16(v);
            efh[base + c] = h;
            efl[base + c] = __float2bfloat16(v - __bfloat162float(h));
        }
    } else if (blk < f_end) {
        int i = (blk - e_end) * 256 + tid;
        uint4 z = {0u, 0u, 0u, 0u};
        int nef = B * 516 * 16;
        int nh  = B * 516 * 8;
        if (i < nef) {
            int c = i % 16, t = i / 16, p = t % 516, b = t / 516;
            int y, xx;
            border_yx(p, y, xx);
            size_t base = ((size_t)(b * HP + y) * HP + xx) * 128;
            reinterpret_cast<uint4*>(efh + base)[c] = z;
            reinterpret_cast<uint4*>(efl + base)[c] = z;
        }
        if (i < nh) {
            int c = i % 8, t = i / 8, p = t % 516, b = t / 516;
            int y, xx;
            border_yx(p, y, xx);
            size_t base = ((size_t)(b * HP + y) * HP + xx) * 64;
            reinterpret_cast<uint4*>(h1h + base)[c] = z;
            reinterpret_cast<uint4*>(h1l + base)[c] = z;
            reinterpret_cast<uint4*>(h2h + base)[c] = z;
            reinterpret_cast<uint4*>(h2l + base)[c] = z;
        }
    } else {
        int idx = (blk - f_end) * 256 + tid;
        if (idx < WSEG1) {
            int ci = idx % 128, t = idx / 128, co = t % 64, k = t / 64;
            hilo_store(w1[(co * 128 + ci) * 9 + k], wh1, wl1, idx);
        } else if (idx < WSEG1 + WSEG2) {
            int j = idx - WSEG1;
            int ci = j % 64, t = j / 64, co = t % 64, k = t / 64;
            hilo_store(w2[(co * 64 + ci) * 9 + k], wh2, wl2, j);
        } else if (idx < WSEG1 + WSEG2 + WSEG3) {
            int j = idx - WSEG1 - WSEG2;
            int ci = j % 64, t = j / 64, co = t % 432, k = t / 432;
            hilo_store(w3[(co * 64 + ci) * 9 + k], wh3, wl3, j);
        } else if (idx < WTOT) {
            int j = idx - WSEG1 - WSEG2 - WSEG3;
            int kk = j % 48, t = j / 48, o = t % 64, g = t / 64;
            float v = 0.f;
            if (kk < 36) {
                int k = kk >> 2, c = kk & 3;
                v = wd[(o * 64 + g * 4 + c) * 9 + k];
            }
            hilo_store(v, whd, wld, j);
        }
    }
}

// ---------------- conv1/conv2 via warp MMA, per-dy A staging, paired B loads ----------------
template <int CIN>
__global__ __launch_bounds__(256)
void conv12_hmma_kernel(const __nv_bfloat16* __restrict__ inh, const __nv_bfloat16* __restrict__ inl,
                        const __nv_bfloat16* __restrict__ wbh, const __nv_bfloat16* __restrict__ wbl,
                        const float* __restrict__ bias,
                        __nv_bfloat16* __restrict__ outh, __nv_bfloat16* __restrict__ outl)
{
    constexpr int STRIDE = CIN * 2 + 16;
    constexpr int NU4 = CIN / 8;
    constexpr int KCH = CIN / 16;
    constexpr int OFF_AH = 0;
    constexpr int OFF_AL = 130 * STRIDE;
    constexpr int OFF_BH = 2 * 130 * STRIDE;
    constexpr int OFF_BL = OFF_BH + 64 * STRIDE;

    extern __shared__ char smem[];
    const uint32_t sbase = smem_to_u32(smem);
    const int tid  = threadIdx.x;
    const int mw   = tid / 32;
    const int lane = tid % 32;
    const int y    = blockIdx.x;
    const int b    = blockIdx.y;

    float C[8][4];
    #pragma unroll
    for (int j = 0; j < 8; j++)
        #pragma unroll
        for (int r = 0; r < 4; r++) C[j][r] = 0.f;

    const int a_row   = mw * 16 + (lane & 15);
    const int a_khalf = (lane & 16) ? 16 : 0;
    // paired-B x4 lane mapping: lanes 0-7/8-15 -> j0's k-halves, 16-23/24-31 -> j1's
    const int b4_row  = ((lane >> 4) << 3) + (lane & 7);
    const int b4_kh   = (lane & 8) ? 16 : 0;

    #pragma unroll 1
    for (int dy = 0; dy < 3; dy++) {
        __syncthreads();
        const size_t abase = (size_t)(b * HP + y + dy) * HP * CIN;
        const uint4* gAh = reinterpret_cast<const uint4*>(inh + abase);
        const uint4* gAl = reinterpret_cast<const uint4*>(inl + abase);
        #pragma unroll 1
        for (int i = tid; i < 2 * 130 * NU4; i += 256) {
            int buf = i / (130 * NU4);
            int rem = i - buf * 130 * NU4;
            int r = rem / NU4, c = rem % NU4;
            uint4 v = (buf ? gAl : gAh)[r * NU4 + c];
            *reinterpret_cast<uint4*>(smem + (buf ? OFF_AL : OFF_AH) + r * STRIDE + c * 16) = v;
        }
        {
            const int tap = dy * 3;
            const uint4* gBh = reinterpret_cast<const uint4*>(wbh + (size_t)tap * 64 * CIN);
            const uint4* gBl = reinterpret_cast<const uint4*>(wbl + (size_t)tap * 64 * CIN);
            #pragma unroll 1
            for (int i = tid; i < 2 * 64 * NU4; i += 256) {
                int buf = i / (64 * NU4);
                int rem = i - buf * 64 * NU4;
                int r = rem / NU4, c = rem % NU4;
                uint4 v = (buf ? gBl : gBh)[r * NU4 + c];
                *reinterpret_cast<uint4*>(smem + (buf ? OFF_BL : OFF_BH) + r * STRIDE + c * 16) = v;
            }
        }
        __syncthreads();

        #pragma unroll 1
        for (int dx = 0; dx < 3; dx++) {
            if (dx > 0) {
                __syncthreads();
                const int tap = dy * 3 + dx;
                const uint4* gBh = reinterpret_cast<const uint4*>(wbh + (size_t)tap * 64 * CIN);
                const uint4* gBl = reinterpret_cast<const uint4*>(wbl + (size_t)tap * 64 * CIN);
                #pragma unroll 1
                for (int i = tid; i < 2 * 64 * NU4; i += 256) {
                    int buf = i / (64 * NU4);
                    int rem = i - buf * 64 * NU4;
                    int r = rem / NU4, c = rem % NU4;
                    uint4 v = (buf ? gBl : gBh)[r * NU4 + c];
                    *reinterpret_cast<uint4*>(smem + (buf ? OFF_BL : OFF_BH) + r * STRIDE + c * 16) = v;
                }
                __syncthreads();
            }
            const uint32_t arow_b = (a_row + dx) * STRIDE + a_khalf;
            #pragma unroll 1
            for (int kc = 0; kc < KCH; kc++) {
                const int k0b = kc * 32;
                uint32_t a_h[4], a_l[4];
                ldsm_x4(a_h, sbase + OFF_AH + arow_b + k0b);
                ldsm_x4(a_l, sbase + OFF_AL + arow_b + k0b);
                #pragma unroll
                for (int jp = 0; jp < 4; jp++) {
                    const uint32_t baddr = (uint32_t)(b4_row + jp * 16) * STRIDE + k0b + b4_kh;
                    uint32_t bh[4], bl[4];
                    ldsm_x4(bh, sbase + OFF_BH + baddr);
                    ldsm_x4(bl, sbase + OFF_BL + baddr);
                    mma_bf16_2(C[jp * 2],     a_h, bh[0], bh[1]);
                    mma_bf16_2(C[jp * 2],     a_h, bl[0], bl[1]);
                    mma_bf16_2(C[jp * 2],     a_l, bh[0], bh[1]);
                    mma_bf16_2(C[jp * 2 + 1], a_h, bh[2], bh[3]);
                    mma_bf16_2(C[jp * 2 + 1], a_h, bl[2], bl[3]);
                    mma_bf16_2(C[jp * 2 + 1], a_l, bh[2], bh[3]);
                }
            }
        }
    }

    const int g = lane >> 2, t = lane & 3;
    const int xp0 = mw * 16 + g;
    #pragma unroll
    for (int j = 0; j < 8; j++) {
        #pragma unroll
        for (int r = 0; r < 4; r++) {
            const int co = j * 8 + t * 2 + (r & 1);
            const int xp = (r < 2) ? xp0 : xp0 + 8;
            float v = C[j][r] + __ldg(&bias[co]);
            v = (v >= 0.f) ? v : 0.1f * v;
            __nv_bfloat16 h = __float2bfloat16(v);
            __nv_bfloat16 l = __float2bfloat16(v - __bfloat162float(h));
            size_t base = ((size_t)(b * HP + y + 1) * HP + (xp + 1)) * 64 + co;
            outh[base] = h;
            outl[base] = l;
        }
    }
}

// ---------------- conv3 via warp MMA, per-dy A staging, paired B loads, 2 CTAs/SM ----------------
constexpr int STR3 = 144;
constexpr int OFF_AH3 = 0;
constexpr int OFF_AL3 = 130 * STR3;
constexpr int OFF_BH3 = 2 * 130 * STR3;
constexpr int OFF_BL3 = OFF_BH3 + 144 * STR3;
constexpr int SMEM3_TOTAL = OFF_BL3 + 144 * STR3;  // 78912

__global__ __launch_bounds__(512, 2)
void conv3_hmma_kernel(const __nv_bfloat16* __restrict__ h2ph, const __nv_bfloat16* __restrict__ h2pl,
                       const __nv_bfloat16* __restrict__ wbh, const __nv_bfloat16* __restrict__ wbl,
                       const float* __restrict__ b3, const float* __restrict__ flow,
                       float* __restrict__ po)
{
    extern __shared__ char smem[];
    const uint32_t sbase = smem_to_u32(smem);
    const int tid  = threadIdx.x;
    const int wid  = tid / 32;
    const int lane = tid % 32;
    const int mw   = wid / 2;
    const int wn   = wid % 2;
    const int y    = blockIdx.x;
    const int nt   = blockIdx.y;
    const int b    = blockIdx.z;

    float C[9][4];
    #pragma unroll
    for (int j = 0; j < 9; j++)
        #pragma unroll
        for (int r = 0; r < 4; r++) C[j][r] = 0.f;

    const int a_row = mw * 16 + (lane & 15);
    const int a_khalf = (lane & 16) ? 16 : 0;
    const int bl15 = lane & 15;
    const int b_rowin = bl15 & 7;
    const int b_khalf = (bl15 & 8) ? 16 : 0;
    const int b4_row  = wn * 72 + ((lane >> 4) << 3) + (lane & 7);
    const int b4_kh   = (lane & 8) ? 16 : 0;

    #pragma unroll 1
    for (int dy = 0; dy < 3; dy++) {
        __syncthreads();
        const size_t abase = (size_t)(b * HP + y + dy) * HP * 64;
        const uint4* gAh = reinterpret_cast<const uint4*>(h2ph + abase);
        const uint4* gAl = reinterpret_cast<const uint4*>(h2pl + abase);
        #pragma unroll 1
        for (int i = tid; i < 2 * 130 * 8; i += 512) {
            int buf = i / 1040;
            int rem = i - buf * 1040;
            int r = rem >> 3, c = rem & 7;
            uint4 v = (buf ? gAl : gAh)[r * 8 + c];
            *reinterpret_cast<uint4*>(smem + (buf ? OFF_AL3 : OFF_AH3) + r * STR3 + c * 16) = v;
        }
        {
            const int tap = dy * 3;
            const uint4* gBh = reinterpret_cast<const uint4*>(wbh + ((size_t)tap * 432 + nt * 144) * 64);
            const uint4* gBl = reinterpret_cast<const uint4*>(wbl + ((size_t)tap * 432 + nt * 144) * 64);
            #pragma unroll 1
            for (int i = tid; i < 2304; i += 512) {
                int buf = (i >= 1152) ? 1 : 0;
                int j2  = buf ? i - 1152 : i;
                int r = j2 >> 3, c = j2 & 7;
                uint4 v = (buf ? gBl : gBh)[r * 8 + c];
                *reinterpret_cast<uint4*>(smem + (buf ? OFF_BL3 : OFF_BH3) + r * STR3 + c * 16) = v;
            }
        }
        __syncthreads();

        #pragma unroll 1
        for (int dx = 0; dx < 3; dx++) {
            if (dx > 0) {
                __syncthreads();
                const int tap = dy * 3 + dx;
                const uint4* gBh = reinterpret_cast<const uint4*>(wbh + ((size_t)tap * 432 + nt * 144) * 64);
                const uint4* gBl = reinterpret_cast<const uint4*>(wbl + ((size_t)tap * 432 + nt * 144) * 64);
                #pragma unroll 1
                for (int i = tid; i < 2304; i += 512) {
                    int buf = (i >= 1152) ? 1 : 0;
                    int j2  = buf ? i - 1152 : i;
                    int r = j2 >> 3, c = j2 & 7;
                    uint4 v = (buf ? gBl : gBh)[r * 8 + c];
                    *reinterpret_cast<uint4*>(smem + (buf ? OFF_BL3 : OFF_BH3) + r * STR3 + c * 16) = v;
                }
                __syncthreads();
            }
            const uint32_t arow_b = (a_row + dx) * STR3 + a_khalf;
            #pragma unroll
            for (int kc = 0; kc < 4; kc++) {
                const int k0b = kc * 32;
                uint32_t a_h[4], a_l[4];
                ldsm_x4(a_h, sbase + OFF_AH3 + arow_b + k0b);
                ldsm_x4(a_l, sbase + OFF_AL3 + arow_b + k0b);
                #pragma unroll
                for (int jp = 0; jp < 4; jp++) {
                    const uint32_t baddr = (uint32_t)(b4_row + jp * 16) * STR3 + k0b + b4_kh;
                    uint32_t bh[4], bl[4];
                    ldsm_x4(bh, sbase + OFF_BH3 + baddr);
                    ldsm_x4(bl, sbase + OFF_BL3 + baddr);
                    mma_bf16_2(C[jp * 2],     a_h, bh[0], bh[1]);
                    mma_bf16_2(C[jp * 2],     a_h, bl[0], bl[1]);
                    mma_bf16_2(C[jp * 2],     a_l, bh[0], bh[1]);
                    mma_bf16_2(C[jp * 2 + 1], a_h, bh[2], bh[3]);
                    mma_bf16_2(C[jp * 2 + 1], a_h, bl[2], bl[3]);
                    mma_bf16_2(C[jp * 2 + 1], a_l, bh[2], bh[3]);
                }
                {   // leftover j = 8
                    const int brow = wn * 72 + 64 + b_rowin;
                    uint32_t b_h[2], b_l[2];
                    ldsm_x2(b_h, sbase + OFF_BH3 + brow * STR3 + k0b + b_khalf);
                    ldsm_x2(b_l, sbase + OFF_BL3 + brow * STR3 + k0b + b_khalf);
                    mma_bf16(C[8], a_h, b_h);
                    mma_bf16(C[8], a_h, b_l);
                    mma_bf16(C[8], a_l, b_h);
                }
            }
        }
    }

    const int g = lane >> 2, t = lane & 3;
    const int hw0 = y * Wc + mw * 16 + g;
    const int hw1 = hw0 + 8;
    const float fy0 = flow[(b * 2 + 1) * HWc + hw0];
    const float fx0 = flow[(b * 2 + 0) * HWc + hw0];
    const float fy1 = flow[(b * 2 + 1) * HWc + hw1];
    const float fx1 = flow[(b * 2 + 0) * HWc + hw1];
    #pragma unroll
    for (int j = 0; j < 9; j++) {
        const int cobase = nt * 144 + wn * 72 + j * 8 + t * 2;
        #pragma unroll
        for (int r = 0; r < 4; r++) {
            const int co = cobase + (r & 1);
            const int hw = (r < 2) ? hw0 : hw1;
            float v = C[j][r] + __ldg(&b3[co]);
            if (co < 288) {
                const float fyv = (r < 2) ? fy0 : fy1;
                const float fxv = (r < 2) ? fx0 : fx1;
                v = 10.f * tanhf(v) + ((co & 1) ? fxv : fyv);
            } else {
                v = 1.f / (1.f + expf(-v));
            }
            po[((size_t)b * 432 + co) * HWc + hw] = v;
        }
    }
}

// ---------------- deformable gather + einsum via HMMA, paired B loads ----------------
constexpr int NSPL = 4;
constexpr int GPS  = 16 / NSPL;
constexpr int STRA = 112;
constexpr int DOFF_AH = 0;
constexpr int DOFF_AL = 128 * STRA;
constexpr int DOFF_BH = 2 * 128 * STRA;
constexpr int DOFF_BL = DOFF_BH + 64 * STRA;
constexpr int DSMEM = DOFF_BL + 64 * STRA;    // 43008

__global__ __launch_bounds__(256)
void deform_hmma_kernel(const float* __restrict__ xt, const float* __restrict__ po,
                        const __nv_bfloat16* __restrict__ wdh, const __nv_bfloat16* __restrict__ wdl,
                        float* __restrict__ dp)
{
    extern __shared__ char smem[];
    const uint32_t sbase = smem_to_u32(smem);
    const int tid  = threadIdx.x;
    const int mw   = tid / 32;
    const int lane = tid % 32;
    const int y    = blockIdx.x;
    const int gsp  = blockIdx.y;
    const int b    = blockIdx.z;
    const int B    = gridDim.z;

    float C[8][4];
    #pragma unroll
    for (int j = 0; j < 8; j++)
        #pragma unroll
        for (int r = 0; r < 4; r++) C[j][r] = 0.f;

    #pragma unroll 1
    for (int i = tid; i < 128 * 2 * 6; i += 256) {
        int w = i % 6;
        int r = (i / 6) % 128;
        int buf = i / (6 * 128);
        *reinterpret_cast<uint32_t*>(smem + (buf ? DOFF_AL : DOFF_AH) + r * STRA + 72 + w * 4) = 0u;
    }

    const int a_row   = mw * 16 + (lane & 15);
    const int a_khalf = (lane & 16) ? 16 : 0;
    const int b4_row  = ((lane >> 4) << 3) + (lane & 7);
    const int b4_kh   = (lane & 8) ? 16 : 0;

    const float* pobase = po + (size_t)b * 432 * HWc + y * Wc;
    const float* xtb = xt + (size_t)b * 16 * HWc * 4;

    #pragma unroll 1
    for (int gl = 0; gl < GPS; gl++) {
        const int g = gsp * GPS + gl;
        __syncthreads();

        const uint4* gBh = reinterpret_cast<const uint4*>(wdh + (size_t)g * 64 * 48);
        const uint4* gBl = reinterpret_cast<const uint4*>(wdl + (size_t)g * 64 * 48);
        #pragma unroll 1
        for (int i = tid; i < 2 * 64 * 6; i += 256) {
            int buf = i / 384;
            int rem = i - buf * 384;
            int r = rem / 6, c = rem % 6;
            uint4 v = (buf ? gBl : gBh)[r * 6 + c];
            *reinterpret_cast<uint4*>(smem + (buf ? DOFF_BL : DOFF_BH) + r * STRA + c * 16) = v;
        }

        const float4* xg = reinterpret_cast<const float4*>(xtb + (size_t)g * HWc * 4);
        #pragma unroll 1
        for (int i = tid; i < 9 * 128; i += 256) {
            const int px  = i & 127;
            const int tap = i >> 7;
            const int gk  = g * 9 + tap;
            const float* pob = pobase + px;
            float offy = pob[(2 * gk) * HWc];
            float offx = pob[(2 * gk + 1) * HWc];
            float msk  = pob[(288 + gk) * HWc];

            float py = (float)(y + tap / 3 - 1) + offy;
            float pxf = (float)(px + tap % 3 - 1) + offx;
            float fy = floorf(py), fxv = floorf(pxf);
            int iy0 = (int)fy, ix0 = (int)fxv;
            float wy = py - fy, wx = pxf - fxv;

            bool vy0 = (unsigned)iy0       < (unsigned)Hc;
            bool vy1 = (unsigned)(iy0 + 1) < (unsigned)Hc;
            bool vx0 = (unsigned)ix0       < (unsigned)Wc;
            bool vx1 = (unsigned)(ix0 + 1) < (unsigned)Wc;
            int cy0 = min(max(iy0, 0), Hc - 1), cy1 = min(max(iy0 + 1, 0), Hc - 1);
            int cx0 = min(max(ix0, 0), Wc - 1), cx1 = min(max(ix0 + 1, 0), Wc - 1);

            float w00 = (1.f - wy) * (1.f - wx) * msk; if (!(vy0 && vx0)) w00 = 0.f;
            float w01 = (1.f - wy) * wx        * msk; if (!(vy0 && vx1)) w01 = 0.f;
            float w10 = wy        * (1.f - wx) * msk; if (!(vy1 && vx0)) w10 = 0.f;
            float w11 = wy        * wx         * msk; if (!(vy1 && vx1)) w11 = 0.f;

            float4 p00 = __ldg(xg + cy0 * Wc + cx0);
            float4 p01 = __ldg(xg + cy0 * Wc + cx1);
            float4 p10 = __ldg(xg + cy1 * Wc + cx0);
            float4 p11 = __ldg(xg + cy1 * Wc + cx1);

            float val[4];
            val[0] = w00 * p00.x + w01 * p01.x + w10 * p10.x + w11 * p11.x;
            val[1] = w00 * p00.y + w01 * p01.y + w10 * p10.y + w11 * p11.y;
            val[2] = w00 * p00.z + w01 * p01.z + w10 * p10.z + w11 * p11.z;
            val[3] = w00 * p00.w + w01 * p01.w + w10 * p10.w + w11 * p11.w;

            uint32_t h01, h23, l01, l23;
            {
                __nv_bfloat16 h0 = __float2bfloat16(val[0]);
                __nv_bfloat16 h1 = __float2bfloat16(val[1]);
                __nv_bfloat16 h2 = __float2bfloat16(val[2]);
                __nv_bfloat16 h3 = __float2bfloat16(val[3]);
                __nv_bfloat16 l0 = __float2bfloat16(val[0] - __bfloat162float(h0));
                __nv_bfloat16 l1 = __float2bfloat16(val[1] - __bfloat162float(h1));
                __nv_bfloat16 l2 = __float2bfloat16(val[2] - __bfloat162float(h2));
                __nv_bfloat16 l3 = __float2bfloat16(val[3] - __bfloat162float(h3));
                h01 = (uint32_t)__bfloat16_as_ushort(h0) | ((uint32_t)__bfloat16_as_ushort(h1) << 16);
                h23 = (uint32_t)__bfloat16_as_ushort(h2) | ((uint32_t)__bfloat16_as_ushort(h3) << 16);
                l01 = (uint32_t)__bfloat16_as_ushort(l0) | ((uint32_t)__bfloat16_as_ushort(l1) << 16);
                l23 = (uint32_t)__bfloat16_as_ushort(l2) | ((uint32_t)__bfloat16_as_ushort(l3) << 16);
            }
            uint32_t ao = px * STRA + tap * 8;
            *reinterpret_cast<uint2*>(smem + DOFF_AH + ao) = make_uint2(h01, h23);
            *reinterpret_cast<uint2*>(smem + DOFF_AL + ao) = make_uint2(l01, l23);
        }
        __syncthreads();

        #pragma unroll
        for (int kc = 0; kc < 3; kc++) {
            const int k0b = kc * 32;
            uint32_t a_h[4], a_l[4];
            ldsm_x4(a_h, sbase + DOFF_AH + a_row * STRA + k0b + a_khalf);
            ldsm_x4(a_l, sbase + DOFF_AL + a_row * STRA + k0b + a_khalf);
            #pragma unroll
            for (int jp = 0; jp < 4; jp++) {
                const uint32_t baddr = (uint32_t)(b4_row + jp * 16) * STRA + k0b + b4_kh;
                uint32_t bh[4], bl[4];
                ldsm_x4(bh, sbase + DOFF_BH + baddr);
                ldsm_x4(bl, sbase + DOFF_BL + baddr);
                mma_bf16_2(C[jp * 2],     a_h, bh[0], bh[1]);
                mma_bf16_2(C[jp * 2],     a_h, bl[0], bl[1]);
                mma_bf16_2(C[jp * 2],     a_l, bh[0], bh[1]);
                mma_bf16_2(C[jp * 2 + 1], a_h, bh[2], bh[3]);
                mma_bf16_2(C[jp * 2 + 1], a_h, bl[2], bl[3]);
                mma_bf16_2(C[jp * 2 + 1], a_l, bh[2], bh[3]);
            }
        }
    }

    const int gfrag = lane >> 2, t = lane & 3;
    const int xp0 = mw * 16 + gfrag;
    float* dpo = dp + ((size_t)gsp * B + b) * 64 * HWc + y * Wc;
    #pragma unroll
    for (int j = 0; j < 8; j++) {
        #pragma unroll
        for (int r = 0; r < 4; r++) {
            const int co = j * 8 + t * 2 + (r & 1);
            const int xp = (r < 2) ? xp0 : xp0 + 8;
            dpo[(size_t)co * HWc + xp] = C[j][r];
        }
    }
}

// ---------------- combine partials (4-way) ----------------
__global__ __launch_bounds__(256)
void combine_kernel(const float* __restrict__ dp, float* __restrict__ out, int n4)
{
    int i = blockIdx.x * 256 + threadIdx.x;
    if (i < n4) {
        float4 a0 = reinterpret_cast<const float4*>(dp)[i];
        float4 a1 = reinterpret_cast<const float4*>(dp)[n4 + i];
        float4 a2 = reinterpret_cast<const float4*>(dp)[2 * n4 + i];
        float4 a3 = reinterpret_cast<const float4*>(dp)[3 * n4 + i];
        float4 o;
        o.x = (a0.x + a1.x) + (a2.x + a3.x);
        o.y = (a0.y + a1.y) + (a2.y + a3.y);
        o.z = (a0.z + a1.z) + (a2.z + a3.z);
        o.w = (a0.w + a1.w) + (a2.w + a3.w);
        reinterpret_cast<float4*>(out)[i] = o;
    }
}

// ---------------- launch ----------------
extern "C" void kernel_launch(void* const* d_in, const int* in_sizes, int n_in,
                              void* d_out, int out_size)
{
    const float* x    = (const float*)d_in[0];
    const float* ef   = (const float*)d_in[1];
    const float* flow = (const float*)d_in[2];
    const float* w1   = (const float*)d_in[3];
    const float* b1   = (const float*)d_in[4];
    const float* w2   = (const float*)d_in[5];
    const float* b2   = (const float*)d_in[6];
    const float* w3   = (const float*)d_in[7];
    const float* b3   = (const float*)d_in[8];
    const float* wgt  = (const float*)d_in[9];
    float* out = (float*)d_out;

    const int B = in_sizes[0] / (64 * HWc);  // = 2

    float *ppo, *pxt, *pdp;
    __nv_bfloat16 *pefh, *pefl, *ph1h, *ph1l, *ph2h, *ph2l;
    __nv_bfloat16 *pw1h, *pw1l, *pw2h, *pw2l, *pw3h, *pw3l, *pwdh, *pwdl;
    cudaGetSymbolAddress((void**)&ppo,  g_po);
    cudaGetSymbolAddress((void**)&pxt,  g_xt);
    cudaGetSymbolAddress((void**)&pdp,  g_dp);
    cudaGetSymbolAddress((void**)&pefh, g_efph);
    cudaGetSymbolAddress((void**)&pefl, g_efpl);
    cudaGetSymbolAddress((void**)&ph1h, g_h1ph);
    cudaGetSymbolAddress((void**)&ph1l, g_h1pl);
    cudaGetSymbolAddress((void**)&ph2h, g_h2ph);
    cudaGetSymbolAddress((void**)&ph2l, g_h2pl);
    cudaGetSymbolAddress((void**)&pw1h, g_w1bh);
    cudaGetSymbolAddress((void**)&pw1l, g_w1bl);
    cudaGetSymbolAddress((void**)&pw2h, g_w2bh);
    cudaGetSymbolAddress((void**)&pw2l, g_w2bl);
    cudaGetSymbolAddress((void**)&pw3h, g_w3bh);
    cudaGetSymbolAddress((void**)&pw3l, g_w3bl);
    cudaGetSymbolAddress((void**)&pwdh, g_wdh);
    cudaGetSymbolAddress((void**)&pwdl, g_wdl);

    constexpr int STR1 = 128 * 2 + 16;
    constexpr int STR2 = 64 * 2 + 16;
    constexpr int SMEM1 = 2 * 130 * STR1 + 2 * 64 * STR1;
    constexpr int SMEM2 = 2 * 130 * STR2 + 2 * 64 * STR2;
    cudaFuncSetAttribute(conv12_hmma_kernel<128>, cudaFuncAttributeMaxDynamicSharedMemorySize, SMEM1);
    cudaFuncSetAttribute(conv12_hmma_kernel<64>,  cudaFuncAttributeMaxDynamicSharedMemorySize, SMEM2);
    cudaFuncSetAttribute(conv3_hmma_kernel, cudaFuncAttributeMaxDynamicSharedMemorySize, SMEM3_TOTAL);
    cudaFuncSetAttribute(deform_hmma_kernel, cudaFuncAttributeMaxDynamicSharedMemorySize, DSMEM);

    // fused prep (1 launch)
    int t_end = 1024 * B;
    int e_end = t_end + 2048 * B;
    int f_end = e_end + (B * 8256 + 255) / 256;
    int total = f_end + (WTOT + 255) / 256;
    prep_all_kernel<<<total, 256>>>(x, pxt, ef, pefh, pefl, ph1h, ph1l, ph2h, ph2l,
                                    w1, w2, w3, wgt,
                                    pw1h, pw1l, pw2h, pw2l, pw3h, pw3l, pwdh, pwdl,
                                    B, t_end, e_end, f_end);

    // conv chain (all HMMA)
    conv12_hmma_kernel<128><<<dim3(Hc, B), 256, SMEM1>>>(pefh, pefl, pw1h, pw1l, b1, ph1h, ph1l);
    conv12_hmma_kernel<64><<<dim3(Hc, B), 256, SMEM2>>>(ph1h, ph1l, pw2h, pw2l, b2, ph2h, ph2l);
    conv3_hmma_kernel<<<dim3(Hc, 3, B), 512, SMEM3_TOTAL>>>(ph2h, ph2l, pw3h, pw3l, b3, flow, ppo);

    // deformable gather + einsum via HMMA
    deform_hmma_kernel<<<dim3(Hc, NSPL, B), 256, DSMEM>>>(pxt, ppo, pwdh, pwdl, pdp);
    int n4 = B * 64 * HWc / 4;
    combine_kernel<<<(n4 + 255) / 256, 256>>>(pdp, out, n4);
}